// round 6
// baseline (speedup 1.0000x reference)
#include <cuda_runtime.h>
#include <cuda_bf16.h>
#include <cstdint>

#define NMAX 8192
#define D 256
#define KP 768                 // 3x-split K: A'=[hi|lo|hi], B'=[hi|hi|lo]
#define MARGIN 0.2f
#define FULLW 0xFFFFFFFFu

// ---------------------------------------------------------------------------
// Scratch (allocation-free rule: __device__ globals)
// ---------------------------------------------------------------------------
__device__ float g_diag[NMAX];
__device__ int   g_rank1[NMAX];
__device__ int   g_rank2[NMAX];
__device__ int   g_rowcost[NMAX];   // float bits, values >= 0
__device__ int   g_colcost[NMAX];   // float bits, values >= 0
__device__ float g_A[NMAX * KP];    // 24 MB
__device__ float g_B[NMAX * KP];    // 24 MB

// ---------------------------------------------------------------------------
// helpers
// ---------------------------------------------------------------------------
__device__ __forceinline__ uint32_t smem_u32(const void* p) {
    uint32_t a;
    asm("{ .reg .u64 t; cvta.to.shared.u64 t, %1; cvt.u32.u64 %0, t; }"
        : "=r"(a) : "l"(p));
    return a;
}
__device__ __forceinline__ float tf32r(float x) {
    uint32_t u;
    asm("cvt.rna.tf32.f32 %0, %1;" : "=r"(u) : "f"(x));
    return __uint_as_float(u);
}
__device__ __forceinline__ void cp16(uint32_t dst, const void* src) {
    asm volatile("cp.async.cg.shared.global [%0], [%1], 16;"
                 :: "r"(dst), "l"(src));
}
__device__ __forceinline__ void mma_tf32(float* d, const uint32_t* a, const uint32_t* b) {
    asm volatile(
        "mma.sync.aligned.m16n8k8.row.col.f32.tf32.tf32.f32 "
        "{%0,%1,%2,%3}, {%4,%5,%6,%7}, {%8,%9}, {%0,%1,%2,%3};"
        : "+f"(d[0]), "+f"(d[1]), "+f"(d[2]), "+f"(d[3])
        : "r"(a[0]), "r"(a[1]), "r"(a[2]), "r"(a[3]), "r"(b[0]), "r"(b[1]));
}

// ---------------------------------------------------------------------------
// init: zero scratch + output
// ---------------------------------------------------------------------------
__global__ void init_kernel(float* out, int n) {
    int i = blockIdx.x * blockDim.x + threadIdx.x;
    if (i < n) {
        g_rank1[i] = 0; g_rank2[i] = 0;
        g_rowcost[i] = 0; g_colcost[i] = 0;
    }
    if (i == 0) out[0] = 0.0f;
}

// ---------------------------------------------------------------------------
// split: A' = [hi|lo|hi], B' = [hi|hi|lo] (tf32-rounded split of fp32)
// ---------------------------------------------------------------------------
__global__ void split_kernel(const float* __restrict__ im, const float* __restrict__ s) {
    int g = blockIdx.x * blockDim.x + threadIdx.x;   // 0 .. 8192*64-1
    int row = g >> 6, c4 = g & 63;
    size_t src = (size_t)row * D + c4 * 4;
    size_t dst = (size_t)row * KP + c4 * 4;

    float4 a = *(const float4*)(im + src);
    float4 ah, al;
    ah.x = tf32r(a.x); al.x = tf32r(a.x - ah.x);
    ah.y = tf32r(a.y); al.y = tf32r(a.y - ah.y);
    ah.z = tf32r(a.z); al.z = tf32r(a.z - ah.z);
    ah.w = tf32r(a.w); al.w = tf32r(a.w - ah.w);
    *(float4*)(g_A + dst)       = ah;
    *(float4*)(g_A + dst + 256) = al;
    *(float4*)(g_A + dst + 512) = ah;

    float4 b = *(const float4*)(s + src);
    float4 bh, bl;
    bh.x = tf32r(b.x); bl.x = tf32r(b.x - bh.x);
    bh.y = tf32r(b.y); bl.y = tf32r(b.y - bh.y);
    bh.z = tf32r(b.z); bl.z = tf32r(b.z - bh.z);
    bh.w = tf32r(b.w); bl.w = tf32r(b.w - bh.w);
    *(float4*)(g_B + dst)       = bh;
    *(float4*)(g_B + dst + 256) = bh;
    *(float4*)(g_B + dst + 512) = bl;
}

// ---------------------------------------------------------------------------
// diag_i = <im_i, s_i> in fp32, one warp per row
// ---------------------------------------------------------------------------
__global__ void diag_kernel(const float* __restrict__ im,
                            const float* __restrict__ s, int n) {
    int warp = (blockIdx.x * blockDim.x + threadIdx.x) >> 5;
    int lane = threadIdx.x & 31;
    if (warp >= n) return;
    const float4* a = (const float4*)(im + (size_t)warp * D);
    const float4* b = (const float4*)(s  + (size_t)warp * D);
    float acc = 0.0f;
#pragma unroll
    for (int k = lane; k < D / 4; k += 32) {
        float4 x = a[k], y = b[k];
        acc += x.x * y.x + x.y * y.y + x.z * y.z + x.w * y.w;
    }
#pragma unroll
    for (int o = 16; o > 0; o >>= 1) acc += __shfl_xor_sync(FULLW, acc, o);
    if (lane == 0) g_diag[warp] = acc;
}

// ---------------------------------------------------------------------------
// Fused mma.sync tf32 tile kernel: 256x128 score tile per CTA.
// 512 threads / 16 warps (8 M x 2 N), warp tile 32x64, m16n8k8,
// K=768, BK=32, double-buffered cp.async stages.
// Smem rows padded to 36 words (conflict-free LDS fragments + STS).
// ---------------------------------------------------------------------------
#define BM 256
#define BN 128
#define BK 32
#define ROWPAD 36
#define NSTAGE (KP / BK)        // 24
#define AS_WORDS (BM * ROWPAD)  // 9216 per stage
#define BS_WORDS (BN * ROWPAD)  // 4608 per stage
#define AS_OFF 0
#define BS_OFF (2 * AS_WORDS)                 // 18432
#define DIAGR_OFF (BS_OFF + 2 * BS_WORDS)     // 27648
#define DIAGC_OFF (DIAGR_OFF + 256)
#define RCNT_OFF  (DIAGC_OFF + 128)
#define RMAX_OFF  (RCNT_OFF + 256)
#define CCNT_OFF  (RMAX_OFF + 256)
#define CMAX_OFF  (CCNT_OFF + 128)
#define SMEM_WORDS (CMAX_OFF + 128)           // 28800
#define SMEM_BYTES (SMEM_WORDS * 4)           // 115200

__global__ __launch_bounds__(512, 1)
void tile_kernel() {
    extern __shared__ __align__(16) float smem[];
    uint32_t* smu = (uint32_t*)smem;
    int* sRCnt = (int*)(smem + RCNT_OFF);
    int* sRMax = (int*)(smem + RMAX_OFF);
    int* sCCnt = (int*)(smem + CCNT_OFF);
    int* sCMax = (int*)(smem + CMAX_OFF);

    const int tid  = threadIdx.x;
    const int wid  = tid >> 5;
    const int lane = tid & 31;
    const int wm   = wid >> 1;          // 0..7 -> M offset wm*32
    const int wn   = wid & 1;           // 0..1 -> N offset wn*64
    const int grp  = lane >> 2;         // 0..7
    const int tig  = lane & 3;          // 0..3
    const int i0 = blockIdx.y * BM;
    const int j0 = blockIdx.x * BN;
    const uint32_t sb = smem_u32(smem);

    // stats init + diag preload
    if (tid < 256) {
        smem[DIAGR_OFF + tid] = g_diag[i0 + tid];
        sRCnt[tid] = 0; sRMax[tid] = 0;
    }
    if (tid < 128) {
        smem[DIAGC_OFF + tid] = g_diag[j0 + tid];
        sCCnt[tid] = 0; sCMax[tid] = 0;
    }
    __syncthreads();

    float acc[2][8][4];
#pragma unroll
    for (int mt = 0; mt < 2; mt++)
#pragma unroll
        for (int nt = 0; nt < 8; nt++)
#pragma unroll
            for (int e = 0; e < 4; e++) acc[mt][nt][e] = 0.0f;

    // staging indices: 512 threads, 16B (4-float) chunks, rows of 32 floats
    const int ldrow = tid >> 3;         // 0..63 base row
    const int ldch  = tid & 7;          // chunk within row
    const float* Abase = g_A + (size_t)(i0 + ldrow) * KP + ldch * 4;
    const float* Bbase = g_B + (size_t)(j0 + ldrow) * KP + ldch * 4;

    // ---- prologue: stage 0 ----
    {
        uint32_t adst = sb + (AS_OFF + ldrow * ROWPAD + ldch * 4) * 4;
        uint32_t bdst = sb + (BS_OFF + ldrow * ROWPAD + ldch * 4) * 4;
#pragma unroll
        for (int q = 0; q < 4; q++)      // A: 256 rows
            cp16(adst + q * 64 * ROWPAD * 4, Abase + (size_t)(q * 64) * KP);
#pragma unroll
        for (int q = 0; q < 2; q++)      // B: 128 rows
            cp16(bdst + q * 64 * ROWPAD * 4, Bbase + (size_t)(q * 64) * KP);
        asm volatile("cp.async.commit_group;");
    }

    for (int st = 0; st < NSTAGE; st++) {
        const int cur = st & 1;
        if (st + 1 < NSTAGE) {
            const int nxt = (st + 1) & 1;
            uint32_t adst = sb + (AS_OFF + nxt * AS_WORDS + ldrow * ROWPAD + ldch * 4) * 4;
            uint32_t bdst = sb + (BS_OFF + nxt * BS_WORDS + ldrow * ROWPAD + ldch * 4) * 4;
            const float* as = Abase + (st + 1) * BK;
            const float* bs = Bbase + (st + 1) * BK;
#pragma unroll
            for (int q = 0; q < 4; q++)
                cp16(adst + q * 64 * ROWPAD * 4, as + (size_t)(q * 64) * KP);
#pragma unroll
            for (int q = 0; q < 2; q++)
                cp16(bdst + q * 64 * ROWPAD * 4, bs + (size_t)(q * 64) * KP);
            asm volatile("cp.async.commit_group;");
            asm volatile("cp.async.wait_group 1;");
        } else {
            asm volatile("cp.async.wait_group 0;");
        }
        __syncthreads();

        const uint32_t* As = smu + AS_OFF + cur * AS_WORDS;
        const uint32_t* Bs = smu + BS_OFF + cur * BS_WORDS;
#pragma unroll
        for (int k8 = 0; k8 < BK / 8; k8++) {
            uint32_t afr[2][4];
#pragma unroll
            for (int mt = 0; mt < 2; mt++) {
                const uint32_t* ap = As + (wm * 32 + mt * 16 + grp) * ROWPAD + k8 * 8 + tig;
                afr[mt][0] = ap[0];
                afr[mt][1] = ap[8 * ROWPAD];
                afr[mt][2] = ap[4];
                afr[mt][3] = ap[8 * ROWPAD + 4];
            }
#pragma unroll
            for (int nt = 0; nt < 8; nt++) {
                const uint32_t* bp = Bs + (wn * 64 + nt * 8 + grp) * ROWPAD + k8 * 8 + tig;
                uint32_t bfr[2];
                bfr[0] = bp[0];
                bfr[1] = bp[4];
#pragma unroll
                for (int mt = 0; mt < 2; mt++)
                    mma_tf32(acc[mt][nt], afr[mt], bfr);
            }
        }
        __syncthreads();
    }

    // ---- epilogue ----
    // Row stats: thread's rows = i0 + wm*32 + mt*16 + grp + h*8
#pragma unroll
    for (int mt = 0; mt < 2; mt++) {
#pragma unroll
        for (int h = 0; h < 2; h++) {
            const int rin = wm * 32 + mt * 16 + grp + h * 8;
            const int gi = i0 + rin;
            const float dr = smem[DIAGR_OFF + rin];
            int cnt = 0;
            float rmax = 0.0f;
#pragma unroll
            for (int nt = 0; nt < 8; nt++) {
#pragma unroll
                for (int e = 0; e < 2; e++) {
                    const int cin = wn * 64 + nt * 8 + 2 * tig + e;
                    float v = acc[mt][nt][h * 2 + e];
                    bool od = (gi != j0 + cin);
                    cnt += (od && (v < dr));
                    if (od) rmax = fmaxf(rmax, (MARGIN + v) - dr);
                }
            }
            cnt  += __shfl_xor_sync(FULLW, cnt, 1);
            rmax  = fmaxf(rmax, __shfl_xor_sync(FULLW, rmax, 1));
            cnt  += __shfl_xor_sync(FULLW, cnt, 2);
            rmax  = fmaxf(rmax, __shfl_xor_sync(FULLW, rmax, 2));
            if (tig == 0) {
                atomicAdd(&sRCnt[rin], cnt);
                atomicMax(&sRMax[rin], __float_as_int(rmax));
            }
        }
    }
    // Col stats: thread's cols = j0 + wn*64 + nt*8 + 2*tig + e
#pragma unroll
    for (int nt = 0; nt < 8; nt++) {
#pragma unroll
        for (int e = 0; e < 2; e++) {
            const int cin = wn * 64 + nt * 8 + 2 * tig + e;
            const float dc = smem[DIAGC_OFF + cin];
            int cnt = 0;
            float cmax = 0.0f;
#pragma unroll
            for (int mt = 0; mt < 2; mt++) {
#pragma unroll
                for (int h = 0; h < 2; h++) {
                    const int gi = i0 + wm * 32 + mt * 16 + grp + h * 8;
                    float v = acc[mt][nt][h * 2 + e];
                    bool od = (gi != j0 + cin);
                    cnt += (od && (v < dc));
                    if (od) cmax = fmaxf(cmax, (MARGIN + v) - dc);
                }
            }
            cnt  += __shfl_xor_sync(FULLW, cnt, 4);
            cmax  = fmaxf(cmax, __shfl_xor_sync(FULLW, cmax, 4));
            cnt  += __shfl_xor_sync(FULLW, cnt, 8);
            cmax  = fmaxf(cmax, __shfl_xor_sync(FULLW, cmax, 8));
            cnt  += __shfl_xor_sync(FULLW, cnt, 16);
            cmax  = fmaxf(cmax, __shfl_xor_sync(FULLW, cmax, 16));
            if (grp == 0) {
                atomicAdd(&sCCnt[cin], cnt);
                atomicMax(&sCMax[cin], __float_as_int(cmax));
            }
        }
    }
    __syncthreads();

    if (tid < 256) {
        atomicAdd(&g_rank1[i0 + tid], sRCnt[tid]);
        atomicMax(&g_rowcost[i0 + tid], sRMax[tid]);
    }
    if (tid < 128) {
        atomicAdd(&g_rank2[j0 + tid], sCCnt[tid]);
        atomicMax(&g_colcost[j0 + tid], sCMax[tid]);
    }
}

// ---------------------------------------------------------------------------
// Deterministic final reduction
// ---------------------------------------------------------------------------
__global__ void final_kernel(float* out, int n) {
    __shared__ float red[32];
    const int t = threadIdx.x;
    const int nv = n / 4;
    float sum = 0.0f;
#pragma unroll
    for (int v = 0; v < 2; v++) {
        int i = t + v * 1024;
        if (i < nv) {
            int4 r1 = ((const int4*)g_rank1)[i];
            int4 r2 = ((const int4*)g_rank2)[i];
            int4 rc = ((const int4*)g_rowcost)[i];
            int4 cc = ((const int4*)g_colcost)[i];
            sum += __int_as_float(rc.x) / ((float)r1.x + 1.0f)
                 + __int_as_float(rc.y) / ((float)r1.y + 1.0f)
                 + __int_as_float(rc.z) / ((float)r1.z + 1.0f)
                 + __int_as_float(rc.w) / ((float)r1.w + 1.0f)
                 + __int_as_float(cc.x) / ((float)r2.x + 1.0f)
                 + __int_as_float(cc.y) / ((float)r2.y + 1.0f)
                 + __int_as_float(cc.z) / ((float)r2.z + 1.0f)
                 + __int_as_float(cc.w) / ((float)r2.w + 1.0f);
        }
    }
#pragma unroll
    for (int o = 16; o > 0; o >>= 1) sum += __shfl_xor_sync(FULLW, sum, o);
    if ((t & 31) == 0) red[t >> 5] = sum;
    __syncthreads();
    if (t < 32) {
        float v = red[t];
#pragma unroll
        for (int o = 16; o > 0; o >>= 1) v += __shfl_xor_sync(FULLW, v, o);
        if (t == 0) out[0] = v;
    }
}

// ---------------------------------------------------------------------------
extern "C" void kernel_launch(void* const* d_in, const int* in_sizes, int n_in,
                              void* d_out, int out_size) {
    const float* im = (const float*)d_in[0];
    const float* s  = (const float*)d_in[1];
    float* out = (float*)d_out;
    const int n = in_sizes[0] / D;   // 8192

    cudaFuncSetAttribute(tile_kernel,
                         cudaFuncAttributeMaxDynamicSharedMemorySize, SMEM_BYTES);

    init_kernel<<<(n + 255) / 256, 256>>>(out, n);
    split_kernel<<<(n * (D / 4) + 255) / 256, 256>>>(im, s);
    diag_kernel<<<(n * 32 + 255) / 256, 256>>>(im, s, n);
    dim3 grid(n / BN, n / BM);
    tile_kernel<<<grid, 512, SMEM_BYTES>>>();
    final_kernel<<<1, 1024>>>(out, n);
}

// round 7
// speedup vs baseline: 1.6422x; 1.6422x over previous
#include <cuda_runtime.h>
#include <cuda_fp16.h>
#include <cstdint>

#define NMAX 8192
#define D 256
#define KP 768                 // fp16 2-limb: A'=[h0|h1|h0], B'=[b0|b0|b1]
#define MARGIN 0.2f
#define FULLW 0xFFFFFFFFu

// ---------------------------------------------------------------------------
// Scratch (allocation-free rule: __device__ globals)
// ---------------------------------------------------------------------------
__device__ float  g_diag[NMAX];
__device__ int    g_rank1[NMAX];
__device__ int    g_rank2[NMAX];
__device__ int    g_rowcost[NMAX];   // float bits, values >= 0
__device__ int    g_colcost[NMAX];   // float bits, values >= 0
__device__ __half g_Ah[NMAX * KP];   // 12.6 MB
__device__ __half g_Bh[NMAX * KP];   // 12.6 MB

// ---------------------------------------------------------------------------
// helpers
// ---------------------------------------------------------------------------
__device__ __forceinline__ uint32_t smem_u32(const void* p) {
    uint32_t a;
    asm("{ .reg .u64 t; cvta.to.shared.u64 t, %1; cvt.u32.u64 %0, t; }"
        : "=r"(a) : "l"(p));
    return a;
}
__device__ __forceinline__ void cp16(uint32_t dst, const void* src) {
    asm volatile("cp.async.cg.shared.global [%0], [%1], 16;"
                 :: "r"(dst), "l"(src));
}
__device__ __forceinline__ void mma_f16(float* d, const uint32_t* a, const uint32_t* b) {
    asm volatile(
        "mma.sync.aligned.m16n8k16.row.col.f32.f16.f16.f32 "
        "{%0,%1,%2,%3}, {%4,%5,%6,%7}, {%8,%9}, {%0,%1,%2,%3};"
        : "+f"(d[0]), "+f"(d[1]), "+f"(d[2]), "+f"(d[3])
        : "r"(a[0]), "r"(a[1]), "r"(a[2]), "r"(a[3]), "r"(b[0]), "r"(b[1]));
}
__device__ __forceinline__ uint32_t h2pack(float x, float y) {
    __half2 h = __floats2half2_rn(x, y);
    return *(uint32_t*)&h;
}

// ---------------------------------------------------------------------------
// init: zero scratch + output
// ---------------------------------------------------------------------------
__global__ void init_kernel(float* out, int n) {
    int i = blockIdx.x * blockDim.x + threadIdx.x;
    if (i < n) {
        g_rank1[i] = 0; g_rank2[i] = 0;
        g_rowcost[i] = 0; g_colcost[i] = 0;
    }
    if (i == 0) out[0] = 0.0f;
}

// ---------------------------------------------------------------------------
// split: fp16 2-limb. h0 = fp16(x), h1 = fp16(x - h0).
// A' = [h0 | h1 | h0], B' = [b0 | b0 | b1]  (K = 768 halves)
// ---------------------------------------------------------------------------
__global__ void split_kernel(const float* __restrict__ im, const float* __restrict__ s) {
    int g = blockIdx.x * blockDim.x + threadIdx.x;   // 0 .. 8192*64-1
    int row = g >> 6, c4 = g & 63;
    size_t src = (size_t)row * D + c4 * 4;
    size_t dst = (size_t)row * KP + c4 * 4;          // in halves

    float4 a = *(const float4*)(im + src);
    float h0x = __half2float(__float2half_rn(a.x));
    float h0y = __half2float(__float2half_rn(a.y));
    float h0z = __half2float(__float2half_rn(a.z));
    float h0w = __half2float(__float2half_rn(a.w));
    uint2 hi = make_uint2(h2pack(a.x, a.y), h2pack(a.z, a.w));          // rn(x)
    uint2 lo = make_uint2(h2pack(a.x - h0x, a.y - h0y), h2pack(a.z - h0z, a.w - h0w));
    *(uint2*)(g_Ah + dst)       = hi;
    *(uint2*)(g_Ah + dst + 256) = lo;
    *(uint2*)(g_Ah + dst + 512) = hi;

    float4 b = *(const float4*)(s + src);
    float g0x = __half2float(__float2half_rn(b.x));
    float g0y = __half2float(__float2half_rn(b.y));
    float g0z = __half2float(__float2half_rn(b.z));
    float g0w = __half2float(__float2half_rn(b.w));
    uint2 bhi = make_uint2(h2pack(b.x, b.y), h2pack(b.z, b.w));
    uint2 blo = make_uint2(h2pack(b.x - g0x, b.y - g0y), h2pack(b.z - g0z, b.w - g0w));
    *(uint2*)(g_Bh + dst)       = bhi;
    *(uint2*)(g_Bh + dst + 256) = bhi;
    *(uint2*)(g_Bh + dst + 512) = blo;
}

// ---------------------------------------------------------------------------
// diag_i = <im_i, s_i> in fp32, one warp per row
// ---------------------------------------------------------------------------
__global__ void diag_kernel(const float* __restrict__ im,
                            const float* __restrict__ s, int n) {
    int warp = (blockIdx.x * blockDim.x + threadIdx.x) >> 5;
    int lane = threadIdx.x & 31;
    if (warp >= n) return;
    const float4* a = (const float4*)(im + (size_t)warp * D);
    const float4* b = (const float4*)(s  + (size_t)warp * D);
    float acc = 0.0f;
#pragma unroll
    for (int k = lane; k < D / 4; k += 32) {
        float4 x = a[k], y = b[k];
        acc += x.x * y.x + x.y * y.y + x.z * y.z + x.w * y.w;
    }
#pragma unroll
    for (int o = 16; o > 0; o >>= 1) acc += __shfl_xor_sync(FULLW, acc, o);
    if (lane == 0) g_diag[warp] = acc;
}

// ---------------------------------------------------------------------------
// Fused mma.sync fp16 tile kernel: 256x128 score tile per CTA.
// 8 warps (4 M x 2 N), warp tile 64x64, m16n8k16, K=768 halves, BK=32 halves,
// double-buffered cp.async. Smem rows: 16 words (32 halves) padded to 20
// words -> fragment LDS (20*grp + tig) mod 32 hits 32 distinct banks.
// ---------------------------------------------------------------------------
#define BM 256
#define BN 128
#define BK 32                    // halves per row per stage
#define ROWPAD 20                // uint32 words per row (16 data + 4 pad)
#define NSTAGE (KP / BK)         // 24
#define AS_WORDS (BM * ROWPAD)   // 5120 per stage
#define BS_WORDS (BN * ROWPAD)   // 2560 per stage
#define AS_OFF 0
#define BS_OFF (2 * AS_WORDS)                 // 10240
#define DIAGR_OFF (BS_OFF + 2 * BS_WORDS)     // 15360
#define DIAGC_OFF (DIAGR_OFF + 256)
#define RCNT_OFF  (DIAGC_OFF + 128)
#define RMAX_OFF  (RCNT_OFF + 256)
#define CCNT_OFF  (RMAX_OFF + 256)
#define CMAX_OFF  (CCNT_OFF + 128)
#define SMEM_WORDS (CMAX_OFF + 128)           // 16512
#define SMEM_BYTES (SMEM_WORDS * 4)           // 66048

__global__ __launch_bounds__(256, 1)
void tile_kernel() {
    extern __shared__ __align__(16) float smem[];
    uint32_t* smu = (uint32_t*)smem;
    int* sRCnt = (int*)(smem + RCNT_OFF);
    int* sRMax = (int*)(smem + RMAX_OFF);
    int* sCCnt = (int*)(smem + CCNT_OFF);
    int* sCMax = (int*)(smem + CMAX_OFF);

    const int tid  = threadIdx.x;
    const int wid  = tid >> 5;
    const int lane = tid & 31;
    const int wm   = wid >> 1;          // 0..3 -> M offset wm*64
    const int wn   = wid & 1;           // 0..1 -> N offset wn*64
    const int grp  = lane >> 2;         // 0..7
    const int tig  = lane & 3;          // 0..3
    const int i0 = blockIdx.y * BM;
    const int j0 = blockIdx.x * BN;
    const uint32_t sb = smem_u32(smem);

    smem[DIAGR_OFF + tid] = g_diag[i0 + tid];
    sRCnt[tid] = 0; sRMax[tid] = 0;
    if (tid < 128) {
        smem[DIAGC_OFF + tid] = g_diag[j0 + tid];
        sCCnt[tid] = 0; sCMax[tid] = 0;
    }
    __syncthreads();

    float acc[4][8][4];
#pragma unroll
    for (int mt = 0; mt < 4; mt++)
#pragma unroll
        for (int nt = 0; nt < 8; nt++)
#pragma unroll
            for (int e = 0; e < 4; e++) acc[mt][nt][e] = 0.0f;

    // staging: 16B = 8 halves per cp.async; row stage = 32 halves = 4 chunks
    const int ldrow = tid >> 2;         // 0..63 base row
    const int ldch  = tid & 3;          // chunk within row
    const __half* Abase = g_Ah + (size_t)(i0 + ldrow) * KP + ldch * 8;
    const __half* Bbase = g_Bh + (size_t)(j0 + ldrow) * KP + ldch * 8;

    // ---- prologue: stage 0 ----
    {
        uint32_t adst = sb + (AS_OFF + ldrow * ROWPAD + ldch * 4) * 4;
        uint32_t bdst = sb + (BS_OFF + ldrow * ROWPAD + ldch * 4) * 4;
#pragma unroll
        for (int q = 0; q < 4; q++)      // A: 256 rows, 64 apart
            cp16(adst + q * 64 * ROWPAD * 4, Abase + (size_t)(q * 64) * KP);
#pragma unroll
        for (int q = 0; q < 2; q++)      // B: 128 rows
            cp16(bdst + q * 64 * ROWPAD * 4, Bbase + (size_t)(q * 64) * KP);
        asm volatile("cp.async.commit_group;");
    }

    for (int st = 0; st < NSTAGE; st++) {
        const int cur = st & 1;
        if (st + 1 < NSTAGE) {
            const int nxt = (st + 1) & 1;
            uint32_t adst = sb + (AS_OFF + nxt * AS_WORDS + ldrow * ROWPAD + ldch * 4) * 4;
            uint32_t bdst = sb + (BS_OFF + nxt * BS_WORDS + ldrow * ROWPAD + ldch * 4) * 4;
            const __half* as = Abase + (st + 1) * BK;
            const __half* bs = Bbase + (st + 1) * BK;
#pragma unroll
            for (int q = 0; q < 4; q++)
                cp16(adst + q * 64 * ROWPAD * 4, as + (size_t)(q * 64) * KP);
#pragma unroll
            for (int q = 0; q < 2; q++)
                cp16(bdst + q * 64 * ROWPAD * 4, bs + (size_t)(q * 64) * KP);
            asm volatile("cp.async.commit_group;");
            asm volatile("cp.async.wait_group 1;");
        } else {
            asm volatile("cp.async.wait_group 0;");
        }
        __syncthreads();

        const uint32_t* As = smu + AS_OFF + cur * AS_WORDS;
        const uint32_t* Bs = smu + BS_OFF + cur * BS_WORDS;
#pragma unroll
        for (int k16 = 0; k16 < BK / 16; k16++) {
            uint32_t afr[4][4];
#pragma unroll
            for (int mt = 0; mt < 4; mt++) {
                const uint32_t* ap = As + (wm * 64 + mt * 16 + grp) * ROWPAD + k16 * 8 + tig;
                afr[mt][0] = ap[0];
                afr[mt][1] = ap[8 * ROWPAD];
                afr[mt][2] = ap[4];
                afr[mt][3] = ap[8 * ROWPAD + 4];
            }
#pragma unroll
            for (int nt = 0; nt < 8; nt++) {
                const uint32_t* bp = Bs + (wn * 64 + nt * 8 + grp) * ROWPAD + k16 * 8 + tig;
                uint32_t bfr[2];
                bfr[0] = bp[0];
                bfr[1] = bp[4];
#pragma unroll
                for (int mt = 0; mt < 4; mt++)
                    mma_f16(acc[mt][nt], afr[mt], bfr);
            }
        }
        __syncthreads();
    }

    // ---- epilogue ----
    // Row stats: thread's rows = i0 + wm*64 + mt*16 + grp + h*8
#pragma unroll
    for (int mt = 0; mt < 4; mt++) {
#pragma unroll
        for (int h = 0; h < 2; h++) {
            const int rin = wm * 64 + mt * 16 + grp + h * 8;
            const int gi = i0 + rin;
            const float dr = smem[DIAGR_OFF + rin];
            int cnt = 0;
            float rmax = 0.0f;
#pragma unroll
            for (int nt = 0; nt < 8; nt++) {
#pragma unroll
                for (int e = 0; e < 2; e++) {
                    const int cin = wn * 64 + nt * 8 + 2 * tig + e;
                    float v = acc[mt][nt][h * 2 + e];
                    bool od = (gi != j0 + cin);
                    cnt += (od && (v < dr));
                    if (od) rmax = fmaxf(rmax, (MARGIN + v) - dr);
                }
            }
            cnt  += __shfl_xor_sync(FULLW, cnt, 1);
            rmax  = fmaxf(rmax, __shfl_xor_sync(FULLW, rmax, 1));
            cnt  += __shfl_xor_sync(FULLW, cnt, 2);
            rmax  = fmaxf(rmax, __shfl_xor_sync(FULLW, rmax, 2));
            if (tig == 0) {
                atomicAdd(&sRCnt[rin], cnt);
                atomicMax(&sRMax[rin], __float_as_int(rmax));
            }
        }
    }
    // Col stats: thread's cols = j0 + wn*64 + nt*8 + 2*tig + e
#pragma unroll
    for (int nt = 0; nt < 8; nt++) {
#pragma unroll
        for (int e = 0; e < 2; e++) {
            const int cin = wn * 64 + nt * 8 + 2 * tig + e;
            const float dc = smem[DIAGC_OFF + cin];
            int cnt = 0;
            float cmax = 0.0f;
#pragma unroll
            for (int mt = 0; mt < 4; mt++) {
#pragma unroll
                for (int h = 0; h < 2; h++) {
                    const int gi = i0 + wm * 64 + mt * 16 + grp + h * 8;
                    float v = acc[mt][nt][h * 2 + e];
                    bool od = (gi != j0 + cin);
                    cnt += (od && (v < dc));
                    if (od) cmax = fmaxf(cmax, (MARGIN + v) - dc);
                }
            }
            cnt  += __shfl_xor_sync(FULLW, cnt, 4);
            cmax  = fmaxf(cmax, __shfl_xor_sync(FULLW, cmax, 4));
            cnt  += __shfl_xor_sync(FULLW, cnt, 8);
            cmax  = fmaxf(cmax, __shfl_xor_sync(FULLW, cmax, 8));
            cnt  += __shfl_xor_sync(FULLW, cnt, 16);
            cmax  = fmaxf(cmax, __shfl_xor_sync(FULLW, cmax, 16));
            if (grp == 0) {
                atomicAdd(&sCCnt[cin], cnt);
                atomicMax(&sCMax[cin], __float_as_int(cmax));
            }
        }
    }
    __syncthreads();

    atomicAdd(&g_rank1[i0 + tid], sRCnt[tid]);
    atomicMax(&g_rowcost[i0 + tid], sRMax[tid]);
    if (tid < 128) {
        atomicAdd(&g_rank2[j0 + tid], sCCnt[tid]);
        atomicMax(&g_colcost[j0 + tid], sCMax[tid]);
    }
}

// ---------------------------------------------------------------------------
// Deterministic final reduction
// ---------------------------------------------------------------------------
__global__ void final_kernel(float* out, int n) {
    __shared__ float red[32];
    const int t = threadIdx.x;
    const int nv = n / 4;
    float sum = 0.0f;
#pragma unroll
    for (int v = 0; v < 2; v++) {
        int i = t + v * 1024;
        if (i < nv) {
            int4 r1 = ((const int4*)g_rank1)[i];
            int4 r2 = ((const int4*)g_rank2)[i];
            int4 rc = ((const int4*)g_rowcost)[i];
            int4 cc = ((const int4*)g_colcost)[i];
            sum += __int_as_float(rc.x) / ((float)r1.x + 1.0f)
                 + __int_as_float(rc.y) / ((float)r1.y + 1.0f)
                 + __int_as_float(rc.z) / ((float)r1.z + 1.0f)
                 + __int_as_float(rc.w) / ((float)r1.w + 1.0f)
                 + __int_as_float(cc.x) / ((float)r2.x + 1.0f)
                 + __int_as_float(cc.y) / ((float)r2.y + 1.0f)
                 + __int_as_float(cc.z) / ((float)r2.z + 1.0f)
                 + __int_as_float(cc.w) / ((float)r2.w + 1.0f);
        }
    }
#pragma unroll
    for (int o = 16; o > 0; o >>= 1) sum += __shfl_xor_sync(FULLW, sum, o);
    if ((t & 31) == 0) red[t >> 5] = sum;
    __syncthreads();
    if (t < 32) {
        float v = red[t];
#pragma unroll
        for (int o = 16; o > 0; o >>= 1) v += __shfl_xor_sync(FULLW, v, o);
        if (t == 0) out[0] = v;
    }
}

// ---------------------------------------------------------------------------
extern "C" void kernel_launch(void* const* d_in, const int* in_sizes, int n_in,
                              void* d_out, int out_size) {
    const float* im = (const float*)d_in[0];
    const float* s  = (const float*)d_in[1];
    float* out = (float*)d_out;
    const int n = in_sizes[0] / D;   // 8192

    cudaFuncSetAttribute(tile_kernel,
                         cudaFuncAttributeMaxDynamicSharedMemorySize, SMEM_BYTES);

    init_kernel<<<(n + 255) / 256, 256>>>(out, n);
    split_kernel<<<(n * (D / 4) + 255) / 256, 256>>>(im, s);
    diag_kernel<<<(n * 32 + 255) / 256, 256>>>(im, s, n);
    dim3 grid(n / BN, n / BM);
    tile_kernel<<<grid, 256, SMEM_BYTES>>>();
    final_kernel<<<1, 1024>>>(out, n);
}

// round 8
// speedup vs baseline: 1.8183x; 1.1072x over previous
#include <cuda_runtime.h>
#include <cuda_fp16.h>
#include <cstdint>

#define NMAX 8192
#define D 256
#define KP 768                 // fp16 2-limb: A'=[h0|h1|h0], B'=[b0|b0|b1]
#define MARGIN 0.2f
#define FULLW 0xFFFFFFFFu

// ---------------------------------------------------------------------------
// Scratch (allocation-free rule: __device__ globals)
// ---------------------------------------------------------------------------
__device__ float  g_diag[NMAX];
__device__ int    g_rank1[NMAX];
__device__ int    g_rank2[NMAX];
__device__ int    g_rowcost[NMAX];   // float bits, values >= 0
__device__ int    g_colcost[NMAX];   // float bits, values >= 0
__device__ __half g_Ah[NMAX * KP];   // 12.6 MB
__device__ __half g_Bh[NMAX * KP];   // 12.6 MB

// ---------------------------------------------------------------------------
// helpers
// ---------------------------------------------------------------------------
__device__ __forceinline__ uint32_t smem_u32(const void* p) {
    uint32_t a;
    asm("{ .reg .u64 t; cvta.to.shared.u64 t, %1; cvt.u32.u64 %0, t; }"
        : "=r"(a) : "l"(p));
    return a;
}
__device__ __forceinline__ void cp16(uint32_t dst, const void* src) {
    asm volatile("cp.async.cg.shared.global [%0], [%1], 16;"
                 :: "r"(dst), "l"(src));
}
__device__ __forceinline__ void mma_f16(float* d, const uint32_t* a, const uint32_t* b) {
    asm volatile(
        "mma.sync.aligned.m16n8k16.row.col.f32.f16.f16.f32 "
        "{%0,%1,%2,%3}, {%4,%5,%6,%7}, {%8,%9}, {%0,%1,%2,%3};"
        : "+f"(d[0]), "+f"(d[1]), "+f"(d[2]), "+f"(d[3])
        : "r"(a[0]), "r"(a[1]), "r"(a[2]), "r"(a[3]), "r"(b[0]), "r"(b[1]));
}
__device__ __forceinline__ uint32_t h2pack(float x, float y) {
    __half2 h = __floats2half2_rn(x, y);
    return *(uint32_t*)&h;
}

// ---------------------------------------------------------------------------
// init: zero scratch + output
// ---------------------------------------------------------------------------
__global__ void init_kernel(float* out, int n) {
    int i = blockIdx.x * blockDim.x + threadIdx.x;
    if (i < n) {
        g_rank1[i] = 0; g_rank2[i] = 0;
        g_rowcost[i] = 0; g_colcost[i] = 0;
    }
    if (i == 0) out[0] = 0.0f;
}

// ---------------------------------------------------------------------------
// split: fp16 2-limb. h0 = fp16(x), h1 = fp16(x - h0).
// A' = [h0 | h1 | h0], B' = [b0 | b0 | b1]  (K = 768 halves)
// ---------------------------------------------------------------------------
__global__ void split_kernel(const float* __restrict__ im, const float* __restrict__ s) {
    int g = blockIdx.x * blockDim.x + threadIdx.x;   // 0 .. 8192*64-1
    int row = g >> 6, c4 = g & 63;
    size_t src = (size_t)row * D + c4 * 4;
    size_t dst = (size_t)row * KP + c4 * 4;          // in halves

    float4 a = *(const float4*)(im + src);
    float h0x = __half2float(__float2half_rn(a.x));
    float h0y = __half2float(__float2half_rn(a.y));
    float h0z = __half2float(__float2half_rn(a.z));
    float h0w = __half2float(__float2half_rn(a.w));
    uint2 hi = make_uint2(h2pack(a.x, a.y), h2pack(a.z, a.w));
    uint2 lo = make_uint2(h2pack(a.x - h0x, a.y - h0y), h2pack(a.z - h0z, a.w - h0w));
    *(uint2*)(g_Ah + dst)       = hi;
    *(uint2*)(g_Ah + dst + 256) = lo;
    *(uint2*)(g_Ah + dst + 512) = hi;

    float4 b = *(const float4*)(s + src);
    float g0x = __half2float(__float2half_rn(b.x));
    float g0y = __half2float(__float2half_rn(b.y));
    float g0z = __half2float(__float2half_rn(b.z));
    float g0w = __half2float(__float2half_rn(b.w));
    uint2 bhi = make_uint2(h2pack(b.x, b.y), h2pack(b.z, b.w));
    uint2 blo = make_uint2(h2pack(b.x - g0x, b.y - g0y), h2pack(b.z - g0z, b.w - g0w));
    *(uint2*)(g_Bh + dst)       = bhi;
    *(uint2*)(g_Bh + dst + 256) = bhi;
    *(uint2*)(g_Bh + dst + 512) = blo;
}

// ---------------------------------------------------------------------------
// diag_i = <im_i, s_i> in fp32, one warp per row
// ---------------------------------------------------------------------------
__global__ void diag_kernel(const float* __restrict__ im,
                            const float* __restrict__ s, int n) {
    int warp = (blockIdx.x * blockDim.x + threadIdx.x) >> 5;
    int lane = threadIdx.x & 31;
    if (warp >= n) return;
    const float4* a = (const float4*)(im + (size_t)warp * D);
    const float4* b = (const float4*)(s  + (size_t)warp * D);
    float acc = 0.0f;
#pragma unroll
    for (int k = lane; k < D / 4; k += 32) {
        float4 x = a[k], y = b[k];
        acc += x.x * y.x + x.y * y.y + x.z * y.z + x.w * y.w;
    }
#pragma unroll
    for (int o = 16; o > 0; o >>= 1) acc += __shfl_xor_sync(FULLW, acc, o);
    if (lane == 0) g_diag[warp] = acc;
}

// ---------------------------------------------------------------------------
// Fused mma.sync fp16 tile kernel: 256x128 score tile per CTA.
// 512 threads / 16 warps (8 M x 2 N), warp tile 32x64, m16n8k16,
// K=768 halves, BK=64 halves (128B rows), double-buffered cp.async.
// ROWPAD=36 words: fragment LDS (36g+t) mod 32 = (4g+t) -> 32 distinct banks.
// ---------------------------------------------------------------------------
#define BM 256
#define BN 128
#define BK 64                    // halves per row per stage (128 B)
#define ROWPAD 36                // uint32 words per row (32 data + 4 pad)
#define NSTAGE (KP / BK)         // 12
#define AS_WORDS (BM * ROWPAD)   // 9216 per stage
#define BS_WORDS (BN * ROWPAD)   // 4608 per stage
#define AS_OFF 0
#define BS_OFF (2 * AS_WORDS)                 // 18432
#define DIAGR_OFF (BS_OFF + 2 * BS_WORDS)     // 27648
#define DIAGC_OFF (DIAGR_OFF + 256)
#define RCNT_OFF  (DIAGC_OFF + 128)
#define RMAX_OFF  (RCNT_OFF + 256)
#define CCNT_OFF  (RMAX_OFF + 256)
#define CMAX_OFF  (CCNT_OFF + 128)
#define SMEM_WORDS (CMAX_OFF + 128)           // 28800
#define SMEM_BYTES (SMEM_WORDS * 4)           // 115200

__global__ __launch_bounds__(512, 1)
void tile_kernel() {
    extern __shared__ __align__(16) float smem[];
    uint32_t* smu = (uint32_t*)smem;
    int* sRCnt = (int*)(smem + RCNT_OFF);
    int* sRMax = (int*)(smem + RMAX_OFF);
    int* sCCnt = (int*)(smem + CCNT_OFF);
    int* sCMax = (int*)(smem + CMAX_OFF);

    const int tid  = threadIdx.x;
    const int wid  = tid >> 5;
    const int lane = tid & 31;
    const int wm   = wid >> 1;          // 0..7 -> M offset wm*32
    const int wn   = wid & 1;           // 0..1 -> N offset wn*64
    const int grp  = lane >> 2;         // 0..7
    const int tig  = lane & 3;          // 0..3
    const int i0 = blockIdx.y * BM;
    const int j0 = blockIdx.x * BN;
    const uint32_t sb = smem_u32(smem);

    if (tid < 256) {
        smem[DIAGR_OFF + tid] = g_diag[i0 + tid];
        sRCnt[tid] = 0; sRMax[tid] = 0;
    }
    if (tid < 128) {
        smem[DIAGC_OFF + tid] = g_diag[j0 + tid];
        sCCnt[tid] = 0; sCMax[tid] = 0;
    }
    __syncthreads();

    float acc[2][8][4];
#pragma unroll
    for (int mt = 0; mt < 2; mt++)
#pragma unroll
        for (int nt = 0; nt < 8; nt++)
#pragma unroll
            for (int e = 0; e < 4; e++) acc[mt][nt][e] = 0.0f;

    // staging: 16B = 8 halves per cp.async; row stage = 64 halves = 8 chunks
    const int ldrow = tid >> 3;         // 0..63 base row
    const int ldch  = tid & 7;          // chunk within row
    const __half* Abase = g_Ah + (size_t)(i0 + ldrow) * KP + ldch * 8;
    const __half* Bbase = g_Bh + (size_t)(j0 + ldrow) * KP + ldch * 8;

    // ---- prologue: stage 0 ----
    {
        uint32_t adst = sb + (AS_OFF + ldrow * ROWPAD + ldch * 4) * 4;
        uint32_t bdst = sb + (BS_OFF + ldrow * ROWPAD + ldch * 4) * 4;
#pragma unroll
        for (int q = 0; q < 4; q++)      // A: 256 rows, 64 apart
            cp16(adst + q * 64 * ROWPAD * 4, Abase + (size_t)(q * 64) * KP);
#pragma unroll
        for (int q = 0; q < 2; q++)      // B: 128 rows
            cp16(bdst + q * 64 * ROWPAD * 4, Bbase + (size_t)(q * 64) * KP);
        asm volatile("cp.async.commit_group;");
    }

    for (int st = 0; st < NSTAGE; st++) {
        const int cur = st & 1;
        if (st + 1 < NSTAGE) {
            const int nxt = (st + 1) & 1;
            uint32_t adst = sb + (AS_OFF + nxt * AS_WORDS + ldrow * ROWPAD + ldch * 4) * 4;
            uint32_t bdst = sb + (BS_OFF + nxt * BS_WORDS + ldrow * ROWPAD + ldch * 4) * 4;
            const __half* as = Abase + (st + 1) * BK;
            const __half* bs = Bbase + (st + 1) * BK;
#pragma unroll
            for (int q = 0; q < 4; q++)
                cp16(adst + q * 64 * ROWPAD * 4, as + (size_t)(q * 64) * KP);
#pragma unroll
            for (int q = 0; q < 2; q++)
                cp16(bdst + q * 64 * ROWPAD * 4, bs + (size_t)(q * 64) * KP);
            asm volatile("cp.async.commit_group;");
            asm volatile("cp.async.wait_group 1;");
        } else {
            asm volatile("cp.async.wait_group 0;");
        }
        __syncthreads();

        const uint32_t* As = smu + AS_OFF + cur * AS_WORDS;
        const uint32_t* Bs = smu + BS_OFF + cur * BS_WORDS;
#pragma unroll
        for (int k16 = 0; k16 < BK / 16; k16++) {
            uint32_t afr[2][4];
#pragma unroll
            for (int mt = 0; mt < 2; mt++) {
                const uint32_t* ap = As + (wm * 32 + mt * 16 + grp) * ROWPAD + k16 * 8 + tig;
                afr[mt][0] = ap[0];
                afr[mt][1] = ap[8 * ROWPAD];
                afr[mt][2] = ap[4];
                afr[mt][3] = ap[8 * ROWPAD + 4];
            }
#pragma unroll
            for (int nt = 0; nt < 8; nt++) {
                const uint32_t* bp = Bs + (wn * 64 + nt * 8 + grp) * ROWPAD + k16 * 8 + tig;
                uint32_t bfr[2];
                bfr[0] = bp[0];
                bfr[1] = bp[4];
#pragma unroll
                for (int mt = 0; mt < 2; mt++)
                    mma_f16(acc[mt][nt], afr[mt], bfr);
            }
        }
        __syncthreads();
    }

    // ---- epilogue ----
    // Row stats: thread's rows = i0 + wm*32 + mt*16 + grp + h*8
#pragma unroll
    for (int mt = 0; mt < 2; mt++) {
#pragma unroll
        for (int h = 0; h < 2; h++) {
            const int rin = wm * 32 + mt * 16 + grp + h * 8;
            const int gi = i0 + rin;
            const float dr = smem[DIAGR_OFF + rin];
            int cnt = 0;
            float rmax = 0.0f;
#pragma unroll
            for (int nt = 0; nt < 8; nt++) {
#pragma unroll
                for (int e = 0; e < 2; e++) {
                    const int cin = wn * 64 + nt * 8 + 2 * tig + e;
                    float v = acc[mt][nt][h * 2 + e];
                    bool od = (gi != j0 + cin);
                    cnt += (od && (v < dr));
                    if (od) rmax = fmaxf(rmax, (MARGIN + v) - dr);
                }
            }
            cnt  += __shfl_xor_sync(FULLW, cnt, 1);
            rmax  = fmaxf(rmax, __shfl_xor_sync(FULLW, rmax, 1));
            cnt  += __shfl_xor_sync(FULLW, cnt, 2);
            rmax  = fmaxf(rmax, __shfl_xor_sync(FULLW, rmax, 2));
            if (tig == 0) {
                atomicAdd(&sRCnt[rin], cnt);
                atomicMax(&sRMax[rin], __float_as_int(rmax));
            }
        }
    }
    // Col stats: thread's cols = j0 + wn*64 + nt*8 + 2*tig + e
#pragma unroll
    for (int nt = 0; nt < 8; nt++) {
#pragma unroll
        for (int e = 0; e < 2; e++) {
            const int cin = wn * 64 + nt * 8 + 2 * tig + e;
            const float dc = smem[DIAGC_OFF + cin];
            int cnt = 0;
            float cmax = 0.0f;
#pragma unroll
            for (int mt = 0; mt < 2; mt++) {
#pragma unroll
                for (int h = 0; h < 2; h++) {
                    const int gi = i0 + wm * 32 + mt * 16 + grp + h * 8;
                    float v = acc[mt][nt][h * 2 + e];
                    bool od = (gi != j0 + cin);
                    cnt += (od && (v < dc));
                    if (od) cmax = fmaxf(cmax, (MARGIN + v) - dc);
                }
            }
            cnt  += __shfl_xor_sync(FULLW, cnt, 4);
            cmax  = fmaxf(cmax, __shfl_xor_sync(FULLW, cmax, 4));
            cnt  += __shfl_xor_sync(FULLW, cnt, 8);
            cmax  = fmaxf(cmax, __shfl_xor_sync(FULLW, cmax, 8));
            cnt  += __shfl_xor_sync(FULLW, cnt, 16);
            cmax  = fmaxf(cmax, __shfl_xor_sync(FULLW, cmax, 16));
            if (grp == 0) {
                atomicAdd(&sCCnt[cin], cnt);
                atomicMax(&sCMax[cin], __float_as_int(cmax));
            }
        }
    }
    __syncthreads();

    if (tid < 256) {
        atomicAdd(&g_rank1[i0 + tid], sRCnt[tid]);
        atomicMax(&g_rowcost[i0 + tid], sRMax[tid]);
    }
    if (tid < 128) {
        atomicAdd(&g_rank2[j0 + tid], sCCnt[tid]);
        atomicMax(&g_colcost[j0 + tid], sCMax[tid]);
    }
}

// ---------------------------------------------------------------------------
// Deterministic final reduction
// ---------------------------------------------------------------------------
__global__ void final_kernel(float* out, int n) {
    __shared__ float red[32];
    const int t = threadIdx.x;
    const int nv = n / 4;
    float sum = 0.0f;
#pragma unroll
    for (int v = 0; v < 2; v++) {
        int i = t + v * 1024;
        if (i < nv) {
            int4 r1 = ((const int4*)g_rank1)[i];
            int4 r2 = ((const int4*)g_rank2)[i];
            int4 rc = ((const int4*)g_rowcost)[i];
            int4 cc = ((const int4*)g_colcost)[i];
            sum += __int_as_float(rc.x) / ((float)r1.x + 1.0f)
                 + __int_as_float(rc.y) / ((float)r1.y + 1.0f)
                 + __int_as_float(rc.z) / ((float)r1.z + 1.0f)
                 + __int_as_float(rc.w) / ((float)r1.w + 1.0f)
                 + __int_as_float(cc.x) / ((float)r2.x + 1.0f)
                 + __int_as_float(cc.y) / ((float)r2.y + 1.0f)
                 + __int_as_float(cc.z) / ((float)r2.z + 1.0f)
                 + __int_as_float(cc.w) / ((float)r2.w + 1.0f);
        }
    }
#pragma unroll
    for (int o = 16; o > 0; o >>= 1) sum += __shfl_xor_sync(FULLW, sum, o);
    if ((t & 31) == 0) red[t >> 5] = sum;
    __syncthreads();
    if (t < 32) {
        float v = red[t];
#pragma unroll
        for (int o = 16; o > 0; o >>= 1) v += __shfl_xor_sync(FULLW, v, o);
        if (t == 0) out[0] = v;
    }
}

// ---------------------------------------------------------------------------
extern "C" void kernel_launch(void* const* d_in, const int* in_sizes, int n_in,
                              void* d_out, int out_size) {
    const float* im = (const float*)d_in[0];
    const float* s  = (const float*)d_in[1];
    float* out = (float*)d_out;
    const int n = in_sizes[0] / D;   // 8192

    cudaFuncSetAttribute(tile_kernel,
                         cudaFuncAttributeMaxDynamicSharedMemorySize, SMEM_BYTES);

    init_kernel<<<(n + 255) / 256, 256>>>(out, n);
    split_kernel<<<(n * (D / 4) + 255) / 256, 256>>>(im, s);
    diag_kernel<<<(n * 32 + 255) / 256, 256>>>(im, s, n);
    dim3 grid(n / BN, n / BM);
    tile_kernel<<<grid, 512, SMEM_BYTES>>>();
    final_kernel<<<1, 1024>>>(out, n);
}

// round 9
// speedup vs baseline: 1.9000x; 1.0449x over previous
#include <cuda_runtime.h>
#include <cuda_fp16.h>
#include <cstdint>

#define NMAX 8192
#define D 256
#define KP 768                 // fp16 2-limb: A'=[h0|h1|h0], B'=[b0|b0|b1]
#define MARGIN 0.2f
#define FULLW 0xFFFFFFFFu

// ---------------------------------------------------------------------------
// Scratch (allocation-free rule: __device__ globals)
// ---------------------------------------------------------------------------
__device__ float  g_diag[NMAX];
__device__ int    g_rank1[NMAX];
__device__ int    g_rank2[NMAX];
__device__ int    g_rowcost[NMAX];   // float bits, values >= 0
__device__ int    g_colcost[NMAX];   // float bits, values >= 0
__device__ __half g_Ah[NMAX * KP];   // 12.6 MB
__device__ __half g_Bh[NMAX * KP];   // 12.6 MB

// ---------------------------------------------------------------------------
// helpers
// ---------------------------------------------------------------------------
__device__ __forceinline__ uint32_t smem_u32(const void* p) {
    uint32_t a;
    asm("{ .reg .u64 t; cvta.to.shared.u64 t, %1; cvt.u32.u64 %0, t; }"
        : "=r"(a) : "l"(p));
    return a;
}
__device__ __forceinline__ void cp16(uint32_t dst, const void* src) {
    asm volatile("cp.async.cg.shared.global [%0], [%1], 16;"
                 :: "r"(dst), "l"(src));
}
__device__ __forceinline__ void mma_f16(float* d, const uint32_t* a, const uint32_t* b) {
    asm volatile(
        "mma.sync.aligned.m16n8k16.row.col.f32.f16.f16.f32 "
        "{%0,%1,%2,%3}, {%4,%5,%6,%7}, {%8,%9}, {%0,%1,%2,%3};"
        : "+f"(d[0]), "+f"(d[1]), "+f"(d[2]), "+f"(d[3])
        : "r"(a[0]), "r"(a[1]), "r"(a[2]), "r"(a[3]), "r"(b[0]), "r"(b[1]));
}
__device__ __forceinline__ uint32_t h2pack(float x, float y) {
    __half2 h = __floats2half2_rn(x, y);
    return *(uint32_t*)&h;
}

// ---------------------------------------------------------------------------
// init: zero scratch + output
// ---------------------------------------------------------------------------
__global__ void init_kernel(float* out, int n) {
    int i = blockIdx.x * blockDim.x + threadIdx.x;
    if (i < n) {
        g_rank1[i] = 0; g_rank2[i] = 0;
        g_rowcost[i] = 0; g_colcost[i] = 0;
    }
    if (i == 0) out[0] = 0.0f;
}

// ---------------------------------------------------------------------------
// split: fp16 2-limb. h0 = fp16(x), h1 = fp16(x - h0).
// A' = [h0 | h1 | h0], B' = [b0 | b0 | b1]  (K = 768 halves)
// ---------------------------------------------------------------------------
__global__ void split_kernel(const float* __restrict__ im, const float* __restrict__ s) {
    int g = blockIdx.x * blockDim.x + threadIdx.x;   // 0 .. 8192*64-1
    int row = g >> 6, c4 = g & 63;
    size_t src = (size_t)row * D + c4 * 4;
    size_t dst = (size_t)row * KP + c4 * 4;          // in halves

    float4 a = *(const float4*)(im + src);
    float h0x = __half2float(__float2half_rn(a.x));
    float h0y = __half2float(__float2half_rn(a.y));
    float h0z = __half2float(__float2half_rn(a.z));
    float h0w = __half2float(__float2half_rn(a.w));
    uint2 hi = make_uint2(h2pack(a.x, a.y), h2pack(a.z, a.w));
    uint2 lo = make_uint2(h2pack(a.x - h0x, a.y - h0y), h2pack(a.z - h0z, a.w - h0w));
    *(uint2*)(g_Ah + dst)       = hi;
    *(uint2*)(g_Ah + dst + 256) = lo;
    *(uint2*)(g_Ah + dst + 512) = hi;

    float4 b = *(const float4*)(s + src);
    float g0x = __half2float(__float2half_rn(b.x));
    float g0y = __half2float(__float2half_rn(b.y));
    float g0z = __half2float(__float2half_rn(b.z));
    float g0w = __half2float(__float2half_rn(b.w));
    uint2 bhi = make_uint2(h2pack(b.x, b.y), h2pack(b.z, b.w));
    uint2 blo = make_uint2(h2pack(b.x - g0x, b.y - g0y), h2pack(b.z - g0z, b.w - g0w));
    *(uint2*)(g_Bh + dst)       = bhi;
    *(uint2*)(g_Bh + dst + 256) = bhi;
    *(uint2*)(g_Bh + dst + 512) = blo;
}

// ---------------------------------------------------------------------------
// diag_i = <im_i, s_i> in fp32, one warp per row
// ---------------------------------------------------------------------------
__global__ void diag_kernel(const float* __restrict__ im,
                            const float* __restrict__ s, int n) {
    int warp = (blockIdx.x * blockDim.x + threadIdx.x) >> 5;
    int lane = threadIdx.x & 31;
    if (warp >= n) return;
    const float4* a = (const float4*)(im + (size_t)warp * D);
    const float4* b = (const float4*)(s  + (size_t)warp * D);
    float acc = 0.0f;
#pragma unroll
    for (int k = lane; k < D / 4; k += 32) {
        float4 x = a[k], y = b[k];
        acc += x.x * y.x + x.y * y.y + x.z * y.z + x.w * y.w;
    }
#pragma unroll
    for (int o = 16; o > 0; o >>= 1) acc += __shfl_xor_sync(FULLW, acc, o);
    if (lane == 0) g_diag[warp] = acc;
}

// ---------------------------------------------------------------------------
// Fused mma.sync fp16 tile kernel: 256x128 score tile per CTA.
// 8 warps (4 M x 2 N), warp tile 64x64, m16n8k16, K=768 halves,
// BK=64 halves (128B rows), double-buffered cp.async stages AND
// double-buffered register fragments across k16 steps (hides LDS latency).
// ROWPAD=36 words: fragment LDS (36g+t) mod 32 = (4g+t) -> 32 distinct banks.
// ---------------------------------------------------------------------------
#define BM 256
#define BN 128
#define BK 64                    // halves per row per stage (128 B)
#define ROWPAD 36                // uint32 words per row (32 data + 4 pad)
#define NSTAGE (KP / BK)         // 12
#define AS_WORDS (BM * ROWPAD)   // 9216 per stage
#define BS_WORDS (BN * ROWPAD)   // 4608 per stage
#define AS_OFF 0
#define BS_OFF (2 * AS_WORDS)                 // 18432
#define DIAGR_OFF (BS_OFF + 2 * BS_WORDS)     // 27648
#define DIAGC_OFF (DIAGR_OFF + 256)
#define RCNT_OFF  (DIAGC_OFF + 128)
#define RMAX_OFF  (RCNT_OFF + 256)
#define CCNT_OFF  (RMAX_OFF + 256)
#define CMAX_OFF  (CCNT_OFF + 128)
#define SMEM_WORDS (CMAX_OFF + 128)           // 28800
#define SMEM_BYTES (SMEM_WORDS * 4)           // 115200

__device__ __forceinline__ void load_frags(
    uint32_t fa[4][4], uint32_t fb[8][2],
    const uint32_t* As, const uint32_t* Bs,
    int k16, int wm, int wn, int grp, int tig)
{
#pragma unroll
    for (int mt = 0; mt < 4; mt++) {
        const uint32_t* ap = As + (wm * 64 + mt * 16 + grp) * ROWPAD + k16 * 8 + tig;
        fa[mt][0] = ap[0];
        fa[mt][1] = ap[8 * ROWPAD];
        fa[mt][2] = ap[4];
        fa[mt][3] = ap[8 * ROWPAD + 4];
    }
#pragma unroll
    for (int nt = 0; nt < 8; nt++) {
        const uint32_t* bp = Bs + (wn * 64 + nt * 8 + grp) * ROWPAD + k16 * 8 + tig;
        fb[nt][0] = bp[0];
        fb[nt][1] = bp[4];
    }
}

__global__ __launch_bounds__(256, 1)
void tile_kernel() {
    extern __shared__ __align__(16) float smem[];
    uint32_t* smu = (uint32_t*)smem;
    int* sRCnt = (int*)(smem + RCNT_OFF);
    int* sRMax = (int*)(smem + RMAX_OFF);
    int* sCCnt = (int*)(smem + CCNT_OFF);
    int* sCMax = (int*)(smem + CMAX_OFF);

    const int tid  = threadIdx.x;
    const int wid  = tid >> 5;
    const int lane = tid & 31;
    const int wm   = wid >> 1;          // 0..3 -> M offset wm*64
    const int wn   = wid & 1;           // 0..1 -> N offset wn*64
    const int grp  = lane >> 2;         // 0..7
    const int tig  = lane & 3;          // 0..3
    const int i0 = blockIdx.y * BM;
    const int j0 = blockIdx.x * BN;
    const uint32_t sb = smem_u32(smem);

    smem[DIAGR_OFF + tid] = g_diag[i0 + tid];
    sRCnt[tid] = 0; sRMax[tid] = 0;
    if (tid < 128) {
        smem[DIAGC_OFF + tid] = g_diag[j0 + tid];
        sCCnt[tid] = 0; sCMax[tid] = 0;
    }
    __syncthreads();

    float acc[4][8][4];
#pragma unroll
    for (int mt = 0; mt < 4; mt++)
#pragma unroll
        for (int nt = 0; nt < 8; nt++)
#pragma unroll
            for (int e = 0; e < 4; e++) acc[mt][nt][e] = 0.0f;

    // staging: 16B = 8 halves per cp.async; row stage = 64 halves = 8 chunks
    const int ldrow = tid >> 3;         // 0..31 base row
    const int ldch  = tid & 7;          // chunk within row
    const __half* Abase = g_Ah + (size_t)(i0 + ldrow) * KP + ldch * 8;
    const __half* Bbase = g_Bh + (size_t)(j0 + ldrow) * KP + ldch * 8;

    // ---- prologue: stage 0 ----
    {
        uint32_t adst = sb + (AS_OFF + ldrow * ROWPAD + ldch * 4) * 4;
        uint32_t bdst = sb + (BS_OFF + ldrow * ROWPAD + ldch * 4) * 4;
#pragma unroll
        for (int q = 0; q < 8; q++)      // A: 256 rows, 32 apart
            cp16(adst + q * 32 * ROWPAD * 4, Abase + (size_t)(q * 32) * KP);
#pragma unroll
        for (int q = 0; q < 4; q++)      // B: 128 rows
            cp16(bdst + q * 32 * ROWPAD * 4, Bbase + (size_t)(q * 32) * KP);
        asm volatile("cp.async.commit_group;");
    }

    for (int st = 0; st < NSTAGE; st++) {
        const int cur = st & 1;
        if (st + 1 < NSTAGE) {
            const int nxt = (st + 1) & 1;
            uint32_t adst = sb + (AS_OFF + nxt * AS_WORDS + ldrow * ROWPAD + ldch * 4) * 4;
            uint32_t bdst = sb + (BS_OFF + nxt * BS_WORDS + ldrow * ROWPAD + ldch * 4) * 4;
            const __half* as = Abase + (st + 1) * BK;
            const __half* bs = Bbase + (st + 1) * BK;
#pragma unroll
            for (int q = 0; q < 8; q++)
                cp16(adst + q * 32 * ROWPAD * 4, as + (size_t)(q * 32) * KP);
#pragma unroll
            for (int q = 0; q < 4; q++)
                cp16(bdst + q * 32 * ROWPAD * 4, bs + (size_t)(q * 32) * KP);
            asm volatile("cp.async.commit_group;");
            asm volatile("cp.async.wait_group 1;");
        } else {
            asm volatile("cp.async.wait_group 0;");
        }
        __syncthreads();

        const uint32_t* As = smu + AS_OFF + cur * AS_WORDS;
        const uint32_t* Bs = smu + BS_OFF + cur * BS_WORDS;

        // register-fragment double buffer across the 4 k16 steps
        uint32_t fa[2][4][4], fb[2][8][2];
        load_frags(fa[0], fb[0], As, Bs, 0, wm, wn, grp, tig);
#pragma unroll
        for (int k16 = 0; k16 < BK / 16; k16++) {
            const int c = k16 & 1;
            if (k16 < BK / 16 - 1)
                load_frags(fa[c ^ 1], fb[c ^ 1], As, Bs, k16 + 1, wm, wn, grp, tig);
#pragma unroll
            for (int nt = 0; nt < 8; nt++)
#pragma unroll
                for (int mt = 0; mt < 4; mt++)
                    mma_f16(acc[mt][nt], fa[c][mt], fb[c][nt]);
        }
        __syncthreads();
    }

    // ---- epilogue ----
    // Row stats: thread's rows = i0 + wm*64 + mt*16 + grp + h*8
#pragma unroll
    for (int mt = 0; mt < 4; mt++) {
#pragma unroll
        for (int h = 0; h < 2; h++) {
            const int rin = wm * 64 + mt * 16 + grp + h * 8;
            const int gi = i0 + rin;
            const float dr = smem[DIAGR_OFF + rin];
            int cnt = 0;
            float rmax = 0.0f;
#pragma unroll
            for (int nt = 0; nt < 8; nt++) {
#pragma unroll
                for (int e = 0; e < 2; e++) {
                    const int cin = wn * 64 + nt * 8 + 2 * tig + e;
                    float v = acc[mt][nt][h * 2 + e];
                    bool od = (gi != j0 + cin);
                    cnt += (od && (v < dr));
                    if (od) rmax = fmaxf(rmax, (MARGIN + v) - dr);
                }
            }
            cnt  += __shfl_xor_sync(FULLW, cnt, 1);
            rmax  = fmaxf(rmax, __shfl_xor_sync(FULLW, rmax, 1));
            cnt  += __shfl_xor_sync(FULLW, cnt, 2);
            rmax  = fmaxf(rmax, __shfl_xor_sync(FULLW, rmax, 2));
            if (tig == 0) {
                atomicAdd(&sRCnt[rin], cnt);
                atomicMax(&sRMax[rin], __float_as_int(rmax));
            }
        }
    }
    // Col stats: thread's cols = j0 + wn*64 + nt*8 + 2*tig + e
#pragma unroll
    for (int nt = 0; nt < 8; nt++) {
#pragma unroll
        for (int e = 0; e < 2; e++) {
            const int cin = wn * 64 + nt * 8 + 2 * tig + e;
            const float dc = smem[DIAGC_OFF + cin];
            int cnt = 0;
            float cmax = 0.0f;
#pragma unroll
            for (int mt = 0; mt < 4; mt++) {
#pragma unroll
                for (int h = 0; h < 2; h++) {
                    const int gi = i0 + wm * 64 + mt * 16 + grp + h * 8;
                    float v = acc[mt][nt][h * 2 + e];
                    bool od = (gi != j0 + cin);
                    cnt += (od && (v < dc));
                    if (od) cmax = fmaxf(cmax, (MARGIN + v) - dc);
                }
            }
            cnt  += __shfl_xor_sync(FULLW, cnt, 4);
            cmax  = fmaxf(cmax, __shfl_xor_sync(FULLW, cmax, 4));
            cnt  += __shfl_xor_sync(FULLW, cnt, 8);
            cmax  = fmaxf(cmax, __shfl_xor_sync(FULLW, cmax, 8));
            cnt  += __shfl_xor_sync(FULLW, cnt, 16);
            cmax  = fmaxf(cmax, __shfl_xor_sync(FULLW, cmax, 16));
            if (grp == 0) {
                atomicAdd(&sCCnt[cin], cnt);
                atomicMax(&sCMax[cin], __float_as_int(cmax));
            }
        }
    }
    __syncthreads();

    atomicAdd(&g_rank1[i0 + tid], sRCnt[tid]);
    atomicMax(&g_rowcost[i0 + tid], sRMax[tid]);
    if (tid < 128) {
        atomicAdd(&g_rank2[j0 + tid], sCCnt[tid]);
        atomicMax(&g_colcost[j0 + tid], sCMax[tid]);
    }
}

// ---------------------------------------------------------------------------
// Deterministic final reduction
// ---------------------------------------------------------------------------
__global__ void final_kernel(float* out, int n) {
    __shared__ float red[32];
    const int t = threadIdx.x;
    const int nv = n / 4;
    float sum = 0.0f;
#pragma unroll
    for (int v = 0; v < 2; v++) {
        int i = t + v * 1024;
        if (i < nv) {
            int4 r1 = ((const int4*)g_rank1)[i];
            int4 r2 = ((const int4*)g_rank2)[i];
            int4 rc = ((const int4*)g_rowcost)[i];
            int4 cc = ((const int4*)g_colcost)[i];
            sum += __int_as_float(rc.x) / ((float)r1.x + 1.0f)
                 + __int_as_float(rc.y) / ((float)r1.y + 1.0f)
                 + __int_as_float(rc.z) / ((float)r1.z + 1.0f)
                 + __int_as_float(rc.w) / ((float)r1.w + 1.0f)
                 + __int_as_float(cc.x) / ((float)r2.x + 1.0f)
                 + __int_as_float(cc.y) / ((float)r2.y + 1.0f)
                 + __int_as_float(cc.z) / ((float)r2.z + 1.0f)
                 + __int_as_float(cc.w) / ((float)r2.w + 1.0f);
        }
    }
#pragma unroll
    for (int o = 16; o > 0; o >>= 1) sum += __shfl_xor_sync(FULLW, sum, o);
    if ((t & 31) == 0) red[t >> 5] = sum;
    __syncthreads();
    if (t < 32) {
        float v = red[t];
#pragma unroll
        for (int o = 16; o > 0; o >>= 1) v += __shfl_xor_sync(FULLW, v, o);
        if (t == 0) out[0] = v;
    }
}

// ---------------------------------------------------------------------------
extern "C" void kernel_launch(void* const* d_in, const int* in_sizes, int n_in,
                              void* d_out, int out_size) {
    const float* im = (const float*)d_in[0];
    const float* s  = (const float*)d_in[1];
    float* out = (float*)d_out;
    const int n = in_sizes[0] / D;   // 8192

    cudaFuncSetAttribute(tile_kernel,
                         cudaFuncAttributeMaxDynamicSharedMemorySize, SMEM_BYTES);

    init_kernel<<<(n + 255) / 256, 256>>>(out, n);
    split_kernel<<<(n * (D / 4) + 255) / 256, 256>>>(im, s);
    diag_kernel<<<(n * 32 + 255) / 256, 256>>>(im, s, n);
    dim3 grid(n / BN, n / BM);
    tile_kernel<<<grid, 256, SMEM_BYTES>>>();
    final_kernel<<<1, 1024>>>(out, n);
}

// round 10
// speedup vs baseline: 2.0119x; 1.0589x over previous
#include <cuda_runtime.h>
#include <cuda_fp16.h>
#include <cstdint>

#define NMAX 8192
#define D 256
#define KP 768                 // fp16 2-limb: A'=[h0|h1|h0], B'=[b0|b0|b1]
#define MARGIN 0.2f
#define FULLW 0xFFFFFFFFu

// ---------------------------------------------------------------------------
// Scratch (allocation-free rule: __device__ globals)
// ---------------------------------------------------------------------------
__device__ float  g_diag[NMAX];
__device__ int    g_rank1[NMAX];
__device__ int    g_rank2[NMAX];
__device__ int    g_rowcost[NMAX];   // float bits, values >= 0
__device__ int    g_colcost[NMAX];   // float bits, values >= 0
__device__ __half g_Ah[NMAX * KP];   // 12.6 MB
__device__ __half g_Bh[NMAX * KP];   // 12.6 MB

// ---------------------------------------------------------------------------
// helpers
// ---------------------------------------------------------------------------
__device__ __forceinline__ uint32_t smem_u32(const void* p) {
    uint32_t a;
    asm("{ .reg .u64 t; cvta.to.shared.u64 t, %1; cvt.u32.u64 %0, t; }"
        : "=r"(a) : "l"(p));
    return a;
}
__device__ __forceinline__ void cp16(uint32_t dst, const void* src) {
    asm volatile("cp.async.cg.shared.global [%0], [%1], 16;"
                 :: "r"(dst), "l"(src));
}
__device__ __forceinline__ void mma_f16(float* d, const uint32_t* a, const uint32_t* b) {
    asm volatile(
        "mma.sync.aligned.m16n8k16.row.col.f32.f16.f16.f32 "
        "{%0,%1,%2,%3}, {%4,%5,%6,%7}, {%8,%9}, {%0,%1,%2,%3};"
        : "+f"(d[0]), "+f"(d[1]), "+f"(d[2]), "+f"(d[3])
        : "r"(a[0]), "r"(a[1]), "r"(a[2]), "r"(a[3]), "r"(b[0]), "r"(b[1]));
}
__device__ __forceinline__ uint32_t h2pack(float x, float y) {
    __half2 h = __floats2half2_rn(x, y);
    return *(uint32_t*)&h;
}

// ---------------------------------------------------------------------------
// init: zero scratch + output
// ---------------------------------------------------------------------------
__global__ void init_kernel(float* out, int n) {
    int i = blockIdx.x * blockDim.x + threadIdx.x;
    if (i < n) {
        g_rank1[i] = 0; g_rank2[i] = 0;
        g_rowcost[i] = 0; g_colcost[i] = 0;
    }
    if (i == 0) out[0] = 0.0f;
}

// ---------------------------------------------------------------------------
// split: fp16 2-limb. h0 = fp16(x), h1 = fp16(x - h0).
// A' = [h0 | h1 | h0], B' = [b0 | b0 | b1]  (K = 768 halves)
// ---------------------------------------------------------------------------
__global__ void split_kernel(const float* __restrict__ im, const float* __restrict__ s) {
    int g = blockIdx.x * blockDim.x + threadIdx.x;   // 0 .. 8192*64-1
    int row = g >> 6, c4 = g & 63;
    size_t src = (size_t)row * D + c4 * 4;
    size_t dst = (size_t)row * KP + c4 * 4;          // in halves

    float4 a = *(const float4*)(im + src);
    float h0x = __half2float(__float2half_rn(a.x));
    float h0y = __half2float(__float2half_rn(a.y));
    float h0z = __half2float(__float2half_rn(a.z));
    float h0w = __half2float(__float2half_rn(a.w));
    uint2 hi = make_uint2(h2pack(a.x, a.y), h2pack(a.z, a.w));
    uint2 lo = make_uint2(h2pack(a.x - h0x, a.y - h0y), h2pack(a.z - h0z, a.w - h0w));
    *(uint2*)(g_Ah + dst)       = hi;
    *(uint2*)(g_Ah + dst + 256) = lo;
    *(uint2*)(g_Ah + dst + 512) = hi;

    float4 b = *(const float4*)(s + src);
    float g0x = __half2float(__float2half_rn(b.x));
    float g0y = __half2float(__float2half_rn(b.y));
    float g0z = __half2float(__float2half_rn(b.z));
    float g0w = __half2float(__float2half_rn(b.w));
    uint2 bhi = make_uint2(h2pack(b.x, b.y), h2pack(b.z, b.w));
    uint2 blo = make_uint2(h2pack(b.x - g0x, b.y - g0y), h2pack(b.z - g0z, b.w - g0w));
    *(uint2*)(g_Bh + dst)       = bhi;
    *(uint2*)(g_Bh + dst + 256) = bhi;
    *(uint2*)(g_Bh + dst + 512) = blo;
}

// ---------------------------------------------------------------------------
// diag_i = <im_i, s_i> in fp32, one warp per row
// ---------------------------------------------------------------------------
__global__ void diag_kernel(const float* __restrict__ im,
                            const float* __restrict__ s, int n) {
    int warp = (blockIdx.x * blockDim.x + threadIdx.x) >> 5;
    int lane = threadIdx.x & 31;
    if (warp >= n) return;
    const float4* a = (const float4*)(im + (size_t)warp * D);
    const float4* b = (const float4*)(s  + (size_t)warp * D);
    float acc = 0.0f;
#pragma unroll
    for (int k = lane; k < D / 4; k += 32) {
        float4 x = a[k], y = b[k];
        acc += x.x * y.x + x.y * y.y + x.z * y.z + x.w * y.w;
    }
#pragma unroll
    for (int o = 16; o > 0; o >>= 1) acc += __shfl_xor_sync(FULLW, acc, o);
    if (lane == 0) g_diag[warp] = acc;
}

// ---------------------------------------------------------------------------
// Fused mma.sync fp16 tile kernel: 128x128 score tile per CTA.
// 256 threads / 8 warps (4 M x 2 N), warp tile 32x64, m16n8k16,
// K=768 halves, BK=64 halves, double-buffered cp.async stages.
// 2 CTAs/SM (<=128 regs): one CTA's MMA burst covers the other's
// stage-boundary sync bubble.
// ROWPAD=36 words: fragment LDS (36g+t) mod 32 = (4g+t) -> 32 distinct banks.
// ---------------------------------------------------------------------------
#define BM 128
#define BN 128
#define BK 64                    // halves per row per stage (128 B)
#define ROWPAD 36                // uint32 words per row (32 data + 4 pad)
#define NSTAGE (KP / BK)         // 12
#define AS_WORDS (BM * ROWPAD)   // 4608 per stage
#define BS_WORDS (BN * ROWPAD)   // 4608 per stage
#define AS_OFF 0
#define BS_OFF (2 * AS_WORDS)                 // 9216
#define DIAGR_OFF (BS_OFF + 2 * BS_WORDS)     // 18432
#define DIAGC_OFF (DIAGR_OFF + 128)
#define RCNT_OFF  (DIAGC_OFF + 128)
#define RMAX_OFF  (RCNT_OFF + 128)
#define CCNT_OFF  (RMAX_OFF + 128)
#define CMAX_OFF  (CCNT_OFF + 128)
#define SMEM_WORDS (CMAX_OFF + 128)           // 19200
#define SMEM_BYTES (SMEM_WORDS * 4)           // 76800

__global__ __launch_bounds__(256, 2)
void tile_kernel() {
    extern __shared__ __align__(16) float smem[];
    uint32_t* smu = (uint32_t*)smem;
    int* sRCnt = (int*)(smem + RCNT_OFF);
    int* sRMax = (int*)(smem + RMAX_OFF);
    int* sCCnt = (int*)(smem + CCNT_OFF);
    int* sCMax = (int*)(smem + CMAX_OFF);

    const int tid  = threadIdx.x;
    const int wid  = tid >> 5;
    const int lane = tid & 31;
    const int wm   = wid >> 1;          // 0..3 -> M offset wm*32
    const int wn   = wid & 1;           // 0..1 -> N offset wn*64
    const int grp  = lane >> 2;         // 0..7
    const int tig  = lane & 3;          // 0..3
    const int i0 = blockIdx.y * BM;
    const int j0 = blockIdx.x * BN;
    const uint32_t sb = smem_u32(smem);

    if (tid < 128) {
        smem[DIAGR_OFF + tid] = g_diag[i0 + tid];
        smem[DIAGC_OFF + tid] = g_diag[j0 + tid];
        sRCnt[tid] = 0; sRMax[tid] = 0;
        sCCnt[tid] = 0; sCMax[tid] = 0;
    }
    __syncthreads();

    float acc[2][8][4];
#pragma unroll
    for (int mt = 0; mt < 2; mt++)
#pragma unroll
        for (int nt = 0; nt < 8; nt++)
#pragma unroll
            for (int e = 0; e < 4; e++) acc[mt][nt][e] = 0.0f;

    // staging: 16B = 8 halves per cp.async; row stage = 64 halves = 8 chunks
    const int ldrow = tid >> 3;         // 0..31 base row
    const int ldch  = tid & 7;          // chunk within row
    const __half* Abase = g_Ah + (size_t)(i0 + ldrow) * KP + ldch * 8;
    const __half* Bbase = g_Bh + (size_t)(j0 + ldrow) * KP + ldch * 8;

    // ---- prologue: stage 0 ----
    {
        uint32_t adst = sb + (AS_OFF + ldrow * ROWPAD + ldch * 4) * 4;
        uint32_t bdst = sb + (BS_OFF + ldrow * ROWPAD + ldch * 4) * 4;
#pragma unroll
        for (int q = 0; q < 4; q++)      // A: 128 rows, 32 apart
            cp16(adst + q * 32 * ROWPAD * 4, Abase + (size_t)(q * 32) * KP);
#pragma unroll
        for (int q = 0; q < 4; q++)      // B: 128 rows
            cp16(bdst + q * 32 * ROWPAD * 4, Bbase + (size_t)(q * 32) * KP);
        asm volatile("cp.async.commit_group;");
    }

    for (int st = 0; st < NSTAGE; st++) {
        const int cur = st & 1;
        if (st + 1 < NSTAGE) {
            const int nxt = (st + 1) & 1;
            uint32_t adst = sb + (AS_OFF + nxt * AS_WORDS + ldrow * ROWPAD + ldch * 4) * 4;
            uint32_t bdst = sb + (BS_OFF + nxt * BS_WORDS + ldrow * ROWPAD + ldch * 4) * 4;
            const __half* as = Abase + (st + 1) * BK;
            const __half* bs = Bbase + (st + 1) * BK;
#pragma unroll
            for (int q = 0; q < 4; q++)
                cp16(adst + q * 32 * ROWPAD * 4, as + (size_t)(q * 32) * KP);
#pragma unroll
            for (int q = 0; q < 4; q++)
                cp16(bdst + q * 32 * ROWPAD * 4, bs + (size_t)(q * 32) * KP);
            asm volatile("cp.async.commit_group;");
            asm volatile("cp.async.wait_group 1;");
        } else {
            asm volatile("cp.async.wait_group 0;");
        }
        __syncthreads();

        const uint32_t* As = smu + AS_OFF + cur * AS_WORDS;
        const uint32_t* Bs = smu + BS_OFF + cur * BS_WORDS;
#pragma unroll
        for (int k16 = 0; k16 < BK / 16; k16++) {
            uint32_t fa[2][4], fb[8][2];
#pragma unroll
            for (int mt = 0; mt < 2; mt++) {
                const uint32_t* ap = As + (wm * 32 + mt * 16 + grp) * ROWPAD + k16 * 8 + tig;
                fa[mt][0] = ap[0];
                fa[mt][1] = ap[8 * ROWPAD];
                fa[mt][2] = ap[4];
                fa[mt][3] = ap[8 * ROWPAD + 4];
            }
#pragma unroll
            for (int nt = 0; nt < 8; nt++) {
                const uint32_t* bp = Bs + (wn * 64 + nt * 8 + grp) * ROWPAD + k16 * 8 + tig;
                fb[nt][0] = bp[0];
                fb[nt][1] = bp[4];
            }
#pragma unroll
            for (int nt = 0; nt < 8; nt++)
#pragma unroll
                for (int mt = 0; mt < 2; mt++)
                    mma_f16(acc[mt][nt], fa[mt], fb[nt]);
        }
        __syncthreads();
    }

    // ---- epilogue ----
    // Row stats: thread's rows = i0 + wm*32 + mt*16 + grp + h*8
#pragma unroll
    for (int mt = 0; mt < 2; mt++) {
#pragma unroll
        for (int h = 0; h < 2; h++) {
            const int rin = wm * 32 + mt * 16 + grp + h * 8;
            const int gi = i0 + rin;
            const float dr = smem[DIAGR_OFF + rin];
            int cnt = 0;
            float rmax = 0.0f;
#pragma unroll
            for (int nt = 0; nt < 8; nt++) {
#pragma unroll
                for (int e = 0; e < 2; e++) {
                    const int cin = wn * 64 + nt * 8 + 2 * tig + e;
                    float v = acc[mt][nt][h * 2 + e];
                    bool od = (gi != j0 + cin);
                    cnt += (od && (v < dr));
                    if (od) rmax = fmaxf(rmax, (MARGIN + v) - dr);
                }
            }
            cnt  += __shfl_xor_sync(FULLW, cnt, 1);
            rmax  = fmaxf(rmax, __shfl_xor_sync(FULLW, rmax, 1));
            cnt  += __shfl_xor_sync(FULLW, cnt, 2);
            rmax  = fmaxf(rmax, __shfl_xor_sync(FULLW, rmax, 2));
            if (tig == 0) {
                atomicAdd(&sRCnt[rin], cnt);
                atomicMax(&sRMax[rin], __float_as_int(rmax));
            }
        }
    }
    // Col stats: thread's cols = j0 + wn*64 + nt*8 + 2*tig + e
#pragma unroll
    for (int nt = 0; nt < 8; nt++) {
#pragma unroll
        for (int e = 0; e < 2; e++) {
            const int cin = wn * 64 + nt * 8 + 2 * tig + e;
            const float dc = smem[DIAGC_OFF + cin];
            int cnt = 0;
            float cmax = 0.0f;
#pragma unroll
            for (int mt = 0; mt < 2; mt++) {
#pragma unroll
                for (int h = 0; h < 2; h++) {
                    const int gi = i0 + wm * 32 + mt * 16 + grp + h * 8;
                    float v = acc[mt][nt][h * 2 + e];
                    bool od = (gi != j0 + cin);
                    cnt += (od && (v < dc));
                    if (od) cmax = fmaxf(cmax, (MARGIN + v) - dc);
                }
            }
            cnt  += __shfl_xor_sync(FULLW, cnt, 4);
            cmax  = fmaxf(cmax, __shfl_xor_sync(FULLW, cmax, 4));
            cnt  += __shfl_xor_sync(FULLW, cnt, 8);
            cmax  = fmaxf(cmax, __shfl_xor_sync(FULLW, cmax, 8));
            cnt  += __shfl_xor_sync(FULLW, cnt, 16);
            cmax  = fmaxf(cmax, __shfl_xor_sync(FULLW, cmax, 16));
            if (grp == 0) {
                atomicAdd(&sCCnt[cin], cnt);
                atomicMax(&sCMax[cin], __float_as_int(cmax));
            }
        }
    }
    __syncthreads();

    if (tid < 128) {
        atomicAdd(&g_rank1[i0 + tid], sRCnt[tid]);
        atomicMax(&g_rowcost[i0 + tid], sRMax[tid]);
        atomicAdd(&g_rank2[j0 + tid], sCCnt[tid]);
        atomicMax(&g_colcost[j0 + tid], sCMax[tid]);
    }
}

// ---------------------------------------------------------------------------
// Deterministic final reduction
// ---------------------------------------------------------------------------
__global__ void final_kernel(float* out, int n) {
    __shared__ float red[32];
    const int t = threadIdx.x;
    const int nv = n / 4;
    float sum = 0.0f;
#pragma unroll
    for (int v = 0; v < 2; v++) {
        int i = t + v * 1024;
        if (i < nv) {
            int4 r1 = ((const int4*)g_rank1)[i];
            int4 r2 = ((const int4*)g_rank2)[i];
            int4 rc = ((const int4*)g_rowcost)[i];
            int4 cc = ((const int4*)g_colcost)[i];
            sum += __int_as_float(rc.x) / ((float)r1.x + 1.0f)
                 + __int_as_float(rc.y) / ((float)r1.y + 1.0f)
                 + __int_as_float(rc.z) / ((float)r1.z + 1.0f)
                 + __int_as_float(rc.w) / ((float)r1.w + 1.0f)
                 + __int_as_float(cc.x) / ((float)r2.x + 1.0f)
                 + __int_as_float(cc.y) / ((float)r2.y + 1.0f)
                 + __int_as_float(cc.z) / ((float)r2.z + 1.0f)
                 + __int_as_float(cc.w) / ((float)r2.w + 1.0f);
        }
    }
#pragma unroll
    for (int o = 16; o > 0; o >>= 1) sum += __shfl_xor_sync(FULLW, sum, o);
    if ((t & 31) == 0) red[t >> 5] = sum;
    __syncthreads();
    if (t < 32) {
        float v = red[t];
#pragma unroll
        for (int o = 16; o > 0; o >>= 1) v += __shfl_xor_sync(FULLW, v, o);
        if (t == 0) out[0] = v;
    }
}

// ---------------------------------------------------------------------------
extern "C" void kernel_launch(void* const* d_in, const int* in_sizes, int n_in,
                              void* d_out, int out_size) {
    const float* im = (const float*)d_in[0];
    const float* s  = (const float*)d_in[1];
    float* out = (float*)d_out;
    const int n = in_sizes[0] / D;   // 8192

    cudaFuncSetAttribute(tile_kernel,
                         cudaFuncAttributeMaxDynamicSharedMemorySize, SMEM_BYTES);

    init_kernel<<<(n + 255) / 256, 256>>>(out, n);
    split_kernel<<<(n * (D / 4) + 255) / 256, 256>>>(im, s);
    diag_kernel<<<(n * 32 + 255) / 256, 256>>>(im, s, n);
    dim3 grid(n / BN, n / BM);
    tile_kernel<<<grid, 256, SMEM_BYTES>>>();
    final_kernel<<<1, 1024>>>(out, n);
}